// round 17
// baseline (speedup 1.0000x reference)
#include <cuda_runtime.h>
#include <cuda_fp16.h>
#include <cstdint>

// ---------------------------------------------------------------------------
// 2-layer GCN:  out = Â( relu( Â(xW1)+b1 ) W2 ) + b2,  Â = D^-1/2 (A+I) D^-1/2
// edge_index is INT32.
// GEMM1: HMMA mma.sync (fp16 in, fp32 accum), H1 stored fp16.
// FUSED agg128+GEMM2: per 128-node tile, aggregate layer-1 (relu+bias) into
// SMEM fp16 tile, then MMA with W2 in the same kernel -> g_hh2 (dis-scaled).
// agg64 finishes layer 2 with no per-edge dis. CSR build overlapped w/ GEMM1.
// ---------------------------------------------------------------------------

static constexpr int NN = 100000;
static constexpr int NE = 1600000;
static constexpr int SCAN_B = (NN + 1023) / 1024;   // 98 blocks

__device__ __half g_hh1[(size_t)NN * 128];  // x @ W1                  (fp16)
__device__ __half g_hh2[(size_t)NN * 64];   // dis[row]*(relu(a1)@W2)  (fp16)
__device__ float  g_dis[NN];                // (1+indeg)^-1/2
__device__ int    g_indeg[NN];
__device__ int    g_ppos[NE];               // per-edge rank within its dst
__device__ int    g_bsum[SCAN_B];
__device__ int    g_rowptr[NN + 1];
__device__ int    g_csrc[NE];               // CSR src ids (grouped by dst)
__device__ int    g_barrier;                // scan grid barrier (reset each call)

// ---------------------------------------------------------------------------
// helpers
// ---------------------------------------------------------------------------
__device__ __forceinline__ unsigned h2u(__half2 h) {
    return *reinterpret_cast<unsigned*>(&h);
}
__device__ __forceinline__ float2 u2f2(unsigned u) {
    return __half22float2(*reinterpret_cast<__half2*>(&u));
}
__device__ __forceinline__ void mma16816(float* c, const unsigned* a,
                                         const unsigned* b) {
    asm volatile(
        "mma.sync.aligned.m16n8k16.row.col.f32.f16.f16.f32 "
        "{%0,%1,%2,%3}, {%4,%5,%6,%7}, {%8,%9}, {%0,%1,%2,%3};"
        : "+f"(c[0]), "+f"(c[1]), "+f"(c[2]), "+f"(c[3])
        : "r"(a[0]), "r"(a[1]), "r"(a[2]), "r"(a[3]), "r"(b[0]), "r"(b[1]));
}

// ---------------------------------------------------------------------------
// CSR build (R15-proven forms: 4 edges/thread, max thread parallelism)
// ---------------------------------------------------------------------------
__global__ void k_zero_indeg() {
    int i = blockIdx.x * blockDim.x + threadIdx.x;
    if (i < NN) g_indeg[i] = 0;
    if (i == 0) g_barrier = 0;
}

__global__ void k_count_pos(const int* __restrict__ ei) {
    int i = blockIdx.x * blockDim.x + threadIdx.x;
    if (i < NE / 4) {
        int4 d = ((const int4*)(ei + NE))[i];
        int4 p;
        p.x = atomicAdd(&g_indeg[d.x], 1);
        p.y = atomicAdd(&g_indeg[d.y], 1);
        p.z = atomicAdd(&g_indeg[d.z], 1);
        p.w = atomicAdd(&g_indeg[d.w], 1);
        ((int4*)g_ppos)[i] = p;
    }
}

// single-kernel scan: block scan + all-arrive grid barrier + offset + store.
__global__ void __launch_bounds__(1024) k_scan() {
    __shared__ int wsum[32];
    __shared__ int s_off, s_tot;
    const int t = threadIdx.x, lane = t & 31, wid = t >> 5;
    const int idx = blockIdx.x * 1024 + t;

    int deg = (idx < NN) ? g_indeg[idx] : 0;
    if (idx < NN) g_dis[idx] = rsqrtf((float)(deg + 1));   // fused k_dis

    int s = deg;
#pragma unroll
    for (int o = 1; o < 32; o <<= 1) {
        int n = __shfl_up_sync(0xffffffffu, s, o);
        if (lane >= o) s += n;
    }
    if (lane == 31) wsum[wid] = s;
    __syncthreads();
    if (wid == 0) {
        int ws = wsum[lane];
#pragma unroll
        for (int o = 1; o < 32; o <<= 1) {
            int n = __shfl_up_sync(0xffffffffu, ws, o);
            if (lane >= o) ws += n;
        }
        wsum[lane] = ws;
    }
    __syncthreads();
    const int incl = (wid ? wsum[wid - 1] : 0) + s;

    if (t == 1023) {
        g_bsum[blockIdx.x] = incl;
        __threadfence();
        atomicAdd(&g_barrier, 1);
    }
    if (t == 0) {
        while (atomicAdd(&g_barrier, 0) < SCAN_B) __nanosleep(64);
    }
    __syncthreads();

    if (t < 32) {
        int pre = 0, tot = 0;
        for (int i = t; i < SCAN_B; i += 32) {
            int v = g_bsum[i];
            tot += v;
            if (i < blockIdx.x) pre += v;
        }
#pragma unroll
        for (int o = 16; o; o >>= 1) {
            pre += __shfl_down_sync(0xffffffffu, pre, o);
            tot += __shfl_down_sync(0xffffffffu, tot, o);
        }
        if (t == 0) { s_off = pre; s_tot = tot; }
    }
    __syncthreads();

    if (idx < NN) g_rowptr[idx] = incl - deg + s_off;
    if (blockIdx.x == SCAN_B - 1 && t == 0) g_rowptr[NN] = s_tot;
}

__global__ void k_fill(const int* __restrict__ ei) {
    int i = blockIdx.x * blockDim.x + threadIdx.x;
    if (i < NE / 4) {
        int4 s = ((const int4*)ei)[i];
        int4 d = ((const int4*)(ei + NE))[i];
        int4 p = ((const int4*)g_ppos)[i];
        int r0 = __ldg(&g_rowptr[d.x]);
        int r1 = __ldg(&g_rowptr[d.y]);
        int r2 = __ldg(&g_rowptr[d.z]);
        int r3 = __ldg(&g_rowptr[d.w]);
        g_csrc[r0 + p.x] = s.x;
        g_csrc[r1 + p.y] = s.y;
        g_csrc[r2 + p.z] = s.z;
        g_csrc[r3 + p.w] = s.w;
    }
}

// ---------------------------------------------------------------------------
// GEMM1 (HMMA): g_hh1[M,128] = x[M,128] @ W1[128,128], fp16 store.
// 256 thr = 8 warps (4m x 2n), BM=128, KC=64.
// ---------------------------------------------------------------------------
__global__ void __launch_bounds__(256, 2)
k_gemm1(const float* __restrict__ Ap, const float* __restrict__ W, int M) {
    constexpr int BN  = 128;
    constexpr int K   = 128;
    constexpr int KC  = 64;
    constexpr int BM  = 128;
    constexpr int SA  = KC + 8;          // 72
    constexpr int SB  = KC + 8;
    constexpr int WN  = 64;
    constexpr int NT  = 8;

    __shared__ __half As[BM * SA];
    __shared__ __half Bs[BN * SB];

    const int tid  = threadIdx.x;
    const int wid  = tid >> 5;
    const int lane = tid & 31;
    const int gid  = lane >> 2;
    const int tig  = lane & 3;
    const int wm   = wid >> 1;
    const int wn   = wid & 1;
    const int rowbase = blockIdx.x * BM;

    float acc[2][NT][4];
#pragma unroll
    for (int mi = 0; mi < 2; mi++)
#pragma unroll
        for (int nj = 0; nj < NT; nj++)
#pragma unroll
            for (int q = 0; q < 4; q++) acc[mi][nj][q] = 0.f;

    for (int kk = 0; kk < K; kk += KC) {
        {
            const float4* A4 = (const float4*)Ap;
#pragma unroll
            for (int t = 0; t < 8; t++) {
                int f  = tid + t * 256;
                int r  = f >> 4;
                int c4 = f & 15;
                int grow = rowbase + r;
                float4 v = make_float4(0.f, 0.f, 0.f, 0.f);
                if (grow < M) v = A4[(size_t)grow * 32 + (kk >> 2) + c4];
                uint2 pk;
                pk.x = h2u(__floats2half2_rn(v.x, v.y));
                pk.y = h2u(__floats2half2_rn(v.z, v.w));
                *(uint2*)&As[r * SA + c4 * 4] = pk;
            }
        }
        {
            int n  = tid % BN;
            int kb = (tid / BN) * 32;          // 2 threads per n, 32 k each
#pragma unroll
            for (int i = 0; i < 32; i++) {
                float v = W[(size_t)(kk + kb + i) * BN + n];
                Bs[n * SB + kb + i] = __float2half_rn(v);
            }
        }
        __syncthreads();

#pragma unroll
        for (int ks = 0; ks < KC / 16; ks++) {
            unsigned a[2][4];
#pragma unroll
            for (int mi = 0; mi < 2; mi++) {
                const __half* base =
                    &As[(wm * 32 + mi * 16 + gid) * SA + ks * 16 + tig * 2];
                a[mi][0] = *(const unsigned*)base;
                a[mi][1] = *(const unsigned*)(base + 8 * SA);
                a[mi][2] = *(const unsigned*)(base + 8);
                a[mi][3] = *(const unsigned*)(base + 8 * SA + 8);
            }
#pragma unroll
            for (int nj = 0; nj < NT; nj++) {
                const __half* bb =
                    &Bs[(wn * WN + nj * 8 + gid) * SB + ks * 16 + tig * 2];
                unsigned b[2];
                b[0] = *(const unsigned*)bb;
                b[1] = *(const unsigned*)(bb + 8);
                mma16816(acc[0][nj], a[0], b);
                mma16816(acc[1][nj], a[1], b);
            }
        }
        __syncthreads();
    }

#pragma unroll
    for (int mi = 0; mi < 2; mi++) {
#pragma unroll
        for (int rr = 0; rr < 2; rr++) {
            int grow = rowbase + wm * 32 + mi * 16 + gid + rr * 8;
            if (grow < M) {
#pragma unroll
                for (int nj = 0; nj < NT; nj++) {
                    int n = wn * WN + nj * 8 + tig * 2;
                    *(unsigned*)&g_hh1[(size_t)grow * BN + n] =
                        h2u(__floats2half2_rn(acc[mi][nj][rr * 2],
                                              acc[mi][nj][rr * 2 + 1]));
                }
            }
        }
    }
}

// ---------------------------------------------------------------------------
// FUSED agg128 + GEMM2. One block per 128-node tile, 256 threads.
// Phase 1: 8 warps x 16 nodes — aggregate layer 1 from g_hh1 (fp32 accum),
//          relu(dw*(dw*h+Σ dis_s*h_s)+b1) -> fp16 SMEM tile As[m][k], SA=136.
// Phase 2: HMMA As @ W2 (Bs chunked KC=64), epilogue stores dis-scaled g_hh2.
// ---------------------------------------------------------------------------
__global__ void __launch_bounds__(256, 1)
k_agg_gemm2(const float* __restrict__ b1, const float* __restrict__ W2) {
    constexpr int BM  = 128;
    constexpr int BN  = 64;
    constexpr int K   = 128;
    constexpr int KC  = 64;
    constexpr int SA  = K + 8;           // 136 halfs (272B ≡ 4 words mod 32)
    constexpr int SB  = KC + 8;          // 72
    constexpr int WN  = 32;              // warp n-tile
    constexpr int NT  = 4;

    __shared__ __half As[BM * SA];       // relu(a1) tile [m][k]   (34816 B)
    __shared__ __half Bs[BN * SB];       // W2 chunk [n][k]        ( 9216 B)

    const int tid  = threadIdx.x;
    const int wid  = tid >> 5;
    const int lane = tid & 31;
    const int rowbase = blockIdx.x * BM;

    // ---- phase 1: aggregate 16 nodes per warp into As ----
    const uint2* h8 = (const uint2*)g_hh1;
    const float4 bb = ((const float4*)b1)[lane];
    for (int mi = 0; mi < 16; mi++) {
        const int m = wid * 16 + mi;
        const int w = rowbase + m;
        uint2 pk = make_uint2(0u, 0u);
        if (w < NN) {
            const int beg = g_rowptr[w];
            const int end = g_rowptr[w + 1];
            const float dw = g_dis[w];
            uint2 raw = h8[(size_t)w * 32 + lane];
            float2 f0 = u2f2(raw.x), f1 = u2f2(raw.y);
            float4 acc = make_float4(f0.x * dw, f0.y * dw, f1.x * dw, f1.y * dw);
            int j = beg;
            for (; j + 3 < end; j += 4) {            // 4-way MLP
                int   s0 = g_csrc[j],   s1 = g_csrc[j+1];
                int   s2 = g_csrc[j+2], s3 = g_csrc[j+3];
                float w0 = g_dis[s0],   w1 = g_dis[s1];
                float w2 = g_dis[s2],   w3 = g_dis[s3];
                uint2 r0 = __ldg(h8 + (size_t)s0 * 32 + lane);
                uint2 r1 = __ldg(h8 + (size_t)s1 * 32 + lane);
                uint2 r2 = __ldg(h8 + (size_t)s2 * 32 + lane);
                uint2 r3 = __ldg(h8 + (size_t)s3 * 32 + lane);
                float2 a0 = u2f2(r0.x), c0 = u2f2(r0.y);
                float2 a1 = u2f2(r1.x), c1 = u2f2(r1.y);
                float2 a2 = u2f2(r2.x), c2 = u2f2(r2.y);
                float2 a3 = u2f2(r3.x), c3 = u2f2(r3.y);
                acc.x = fmaf(a0.x, w0, acc.x); acc.y = fmaf(a0.y, w0, acc.y);
                acc.z = fmaf(c0.x, w0, acc.z); acc.w = fmaf(c0.y, w0, acc.w);
                acc.x = fmaf(a1.x, w1, acc.x); acc.y = fmaf(a1.y, w1, acc.y);
                acc.z = fmaf(c1.x, w1, acc.z); acc.w = fmaf(c1.y, w1, acc.w);
                acc.x = fmaf(a2.x, w2, acc.x); acc.y = fmaf(a2.y, w2, acc.y);
                acc.z = fmaf(c2.x, w2, acc.z); acc.w = fmaf(c2.y, w2, acc.w);
                acc.x = fmaf(a3.x, w3, acc.x); acc.y = fmaf(a3.y, w3, acc.y);
                acc.z = fmaf(c3.x, w3, acc.z); acc.w = fmaf(c3.y, w3, acc.w);
            }
            for (; j < end; j++) {
                int   s0 = g_csrc[j];
                float w0 = g_dis[s0];
                uint2 r0 = __ldg(h8 + (size_t)s0 * 32 + lane);
                float2 a0 = u2f2(r0.x), c0 = u2f2(r0.y);
                acc.x = fmaf(a0.x, w0, acc.x); acc.y = fmaf(a0.y, w0, acc.y);
                acc.z = fmaf(c0.x, w0, acc.z); acc.w = fmaf(c0.y, w0, acc.w);
            }
            float rx = fmaxf(fmaf(acc.x, dw, bb.x), 0.f);
            float ry = fmaxf(fmaf(acc.y, dw, bb.y), 0.f);
            float rz = fmaxf(fmaf(acc.z, dw, bb.z), 0.f);
            float rw = fmaxf(fmaf(acc.w, dw, bb.w), 0.f);
            pk.x = h2u(__floats2half2_rn(rx, ry));
            pk.y = h2u(__floats2half2_rn(rz, rw));
        }
        *(uint2*)&As[m * SA + lane * 4] = pk;        // conflict-free
    }
    __syncthreads();

    // ---- phase 2: As @ W2 -> g_hh2 (dis-scaled) ----
    const int gid = lane >> 2;
    const int tig = lane & 3;
    const int wm  = wid >> 1;            // 0..3
    const int wn  = wid & 1;             // 0..1

    float acc[2][NT][4];
#pragma unroll
    for (int mi = 0; mi < 2; mi++)
#pragma unroll
        for (int nj = 0; nj < NT; nj++)
#pragma unroll
            for (int q = 0; q < 4; q++) acc[mi][nj][q] = 0.f;

    for (int kk = 0; kk < K; kk += KC) {
        // load W2 chunk (64 x 64) -> Bs[n][k]
        {
            int n  = tid % BN;
            int kb = (tid / BN) * 16;    // 4 threads per n, 16 k each
#pragma unroll
            for (int i = 0; i < 16; i++) {
                float v = W2[(size_t)(kk + kb + i) * BN + n];
                Bs[n * SB + kb + i] = __float2half_rn(v);
            }
        }
        __syncthreads();

#pragma unroll
        for (int ks = 0; ks < KC / 16; ks++) {
            unsigned a[2][4];
#pragma unroll
            for (int mi = 0; mi < 2; mi++) {
                const __half* base =
                    &As[(wm * 32 + mi * 16 + gid) * SA + kk + ks * 16 + tig * 2];
                a[mi][0] = *(const unsigned*)base;
                a[mi][1] = *(const unsigned*)(base + 8 * SA);
                a[mi][2] = *(const unsigned*)(base + 8);
                a[mi][3] = *(const unsigned*)(base + 8 * SA + 8);
            }
#pragma unroll
            for (int nj = 0; nj < NT; nj++) {
                const __half* bbp =
                    &Bs[(wn * WN + nj * 8 + gid) * SB + ks * 16 + tig * 2];
                unsigned b[2];
                b[0] = *(const unsigned*)bbp;
                b[1] = *(const unsigned*)(bbp + 8);
                mma16816(acc[0][nj], a[0], b);
                mma16816(acc[1][nj], a[1], b);
            }
        }
        __syncthreads();
    }

#pragma unroll
    for (int mi = 0; mi < 2; mi++) {
#pragma unroll
        for (int rr = 0; rr < 2; rr++) {
            int grow = rowbase + wm * 32 + mi * 16 + gid + rr * 8;
            if (grow < NN) {
                float sc = g_dis[grow];
#pragma unroll
                for (int nj = 0; nj < NT; nj++) {
                    int n = wn * WN + nj * 8 + tig * 2;
                    float v0 = acc[mi][nj][rr * 2] * sc;
                    float v1 = acc[mi][nj][rr * 2 + 1] * sc;
                    *(unsigned*)&g_hh2[(size_t)grow * BN + n] =
                        h2u(__floats2half2_rn(v0, v1));
                }
            }
        }
    }
}

// ---------------------------------------------------------------------------
// agg64: out[w] = dw*(hh2[w] + Σ hh2[s]) + b2   (hh2 pre-scaled by dis) fp32
// ---------------------------------------------------------------------------
__global__ void __launch_bounds__(256)
k_agg64(const float* __restrict__ bias, float* __restrict__ outp) {
    const int w = (blockIdx.x * blockDim.x + threadIdx.x) >> 5;
    if (w >= NN) return;
    const int lane = threadIdx.x & 31;
    const int beg = g_rowptr[w];
    const int end = g_rowptr[w + 1];
    const float dw = g_dis[w];

    const unsigned* h4 = (const unsigned*)g_hh2;    // 2 halfs per u32, 32/row
    float2 hv = u2f2(h4[(size_t)w * 32 + lane]);
    float2 acc = hv;
    int j = beg;
    for (; j + 3 < end; j += 4) {
        int s0 = g_csrc[j], s1 = g_csrc[j+1], s2 = g_csrc[j+2], s3 = g_csrc[j+3];
        float2 v0 = u2f2(__ldg(h4 + (size_t)s0 * 32 + lane));
        float2 v1 = u2f2(__ldg(h4 + (size_t)s1 * 32 + lane));
        float2 v2 = u2f2(__ldg(h4 + (size_t)s2 * 32 + lane));
        float2 v3 = u2f2(__ldg(h4 + (size_t)s3 * 32 + lane));
        acc.x += v0.x + v1.x; acc.y += v0.y + v1.y;
        acc.x += v2.x + v3.x; acc.y += v2.y + v3.y;
    }
    for (; j < end; j++) {
        int s0 = g_csrc[j];
        float2 v0 = u2f2(__ldg(h4 + (size_t)s0 * 32 + lane));
        acc.x += v0.x; acc.y += v0.y;
    }
    const float2 bb = ((const float2*)bias)[lane];
    ((float2*)outp)[(size_t)w * 32 + lane] =
        make_float2(fmaf(acc.x, dw, bb.x), fmaf(acc.y, dw, bb.y));
}

// ---------------------------------------------------------------------------
extern "C" void kernel_launch(void* const* d_in, const int* in_sizes, int n_in,
                              void* d_out, int out_size) {
    (void)in_sizes; (void)n_in; (void)out_size;
    const float* x  = (const float*)d_in[0];
    const int*   ei = (const int*)d_in[1];     // int32 (JAX x64 disabled)
    const float* W1 = (const float*)d_in[2];
    const float* b1 = (const float*)d_in[3];
    const float* W2 = (const float*)d_in[4];
    const float* b2 = (const float*)d_in[5];
    float* out = (float*)d_out;

    // fork-join: CSR build on side stream, overlapped with GEMM1
    cudaStream_t s2;
    cudaEvent_t evFork, evJoin;
    cudaStreamCreateWithFlags(&s2, cudaStreamNonBlocking);
    cudaEventCreateWithFlags(&evFork, cudaEventDisableTiming);
    cudaEventCreateWithFlags(&evJoin, cudaEventDisableTiming);

    cudaEventRecord(evFork, 0);
    cudaStreamWaitEvent(s2, evFork, 0);

    // --- CSR branch (stream s2): count+pos, scan(+dis), atomic-free fill ---
    k_zero_indeg<<<(NN + 255) / 256, 256, 0, s2>>>();
    k_count_pos<<<(NE / 4 + 255) / 256, 256, 0, s2>>>(ei);
    k_scan<<<SCAN_B, 1024, 0, s2>>>();
    k_fill<<<(NE / 4 + 255) / 256, 256, 0, s2>>>(ei);
    cudaEventRecord(evJoin, s2);

    // --- main branch (stream 0): GEMM1 overlapped with CSR build ---
    k_gemm1<<<(NN + 127) / 128, 256>>>(x, W1, NN);
    cudaStreamWaitEvent(0, evJoin, 0);

    // fused layer-1 aggregation + layer-2 GEMM, then final aggregation
    k_agg_gemm2<<<(NN + 127) / 128, 256>>>(b1, W2);
    k_agg64<<<(NN * 32 + 255) / 256, 256>>>(b2, out);

    cudaEventDestroy(evFork);
    cudaEventDestroy(evJoin);
    cudaStreamDestroy(s2);
}